// round 1
// baseline (speedup 1.0000x reference)
#include <cuda_runtime.h>
#include <math.h>

#define BATCH   2
#define SEQLEN  8192
#define DMODEL  512
#define DIN     1024
#define NHEADS  16
#define HD      64
#define DSTATE  128
#define CONVD   1280
#define DPROJ   2320
#define NCH     128
#define CH      64

// ---------------- scratch (static device memory; no allocations) ----------------
__device__ float g_zx[(size_t)BATCH*SEQLEN*DPROJ];        // 152 MB  in-proj output (actual token order)
__device__ float g_xBC[(size_t)BATCH*SEQLEN*CONVD];       // 84 MB   conv+silu output (direction-local order)
__device__ float g_dt[(size_t)BATCH*SEQLEN*NHEADS];       // dt (softplus)
__device__ float g_dta[(size_t)BATCH*SEQLEN*NHEADS];      // A*dt
__device__ float g_Atot[BATCH*NHEADS*NCH];                // per-chunk cumsum totals
__device__ float g_states[(size_t)BATCH*NCH*NHEADS*HD*DSTATE]; // 134 MB chunk states / state_in
__device__ float g_y[(size_t)BATCH*SEQLEN*DIN];           // 67 MB   y (direction-local order)
__device__ float g_Wc[2*DMODEL*DIN];                      // fused output weights per direction

// ---------------- generic fp32 GEMM: C[M,N] = A[M,K] @ (BT ? B[N,K]^T : B[K,N]) ----------------
// 128x128 block, BK=8, 256 threads, 8x8 microtile. M%128==0, K%8==0 required; N guarded.
// epi_mode: 0 = plain store. 1 = final write (+bias, row remap). 2 = final accumulate (row remap).
template<bool BT>
__global__ void sgemm128(const float* __restrict__ A, int lda,
                         const float* __restrict__ B, int ldb,
                         float* __restrict__ C, int ldc,
                         int M, int N, int K,
                         const float* __restrict__ bias,
                         int epi_mode, int reverse)
{
    __shared__ float As[8][128];
    __shared__ float Bs[8][128];
    int tid = threadIdx.x;
    int tx = tid & 15, ty = tid >> 4;
    int rowBase = blockIdx.y * 128;
    int colBase = blockIdx.x * 128;
    float acc[8][8];
#pragma unroll
    for (int i = 0; i < 8; i++)
#pragma unroll
        for (int j = 0; j < 8; j++) acc[i][j] = 0.f;

    int ar = tid >> 1;          // 0..127
    int ac = (tid & 1) * 4;     // 0 or 4

    for (int k0 = 0; k0 < K; k0 += 8) {
        // A tile (always valid rows)
        float4 av = *reinterpret_cast<const float4*>(&A[(size_t)(rowBase + ar) * lda + k0 + ac]);
        As[ac + 0][ar] = av.x; As[ac + 1][ar] = av.y; As[ac + 2][ar] = av.z; As[ac + 3][ar] = av.w;
        if (BT) {
            int bn = colBase + ar;
            float4 bv = make_float4(0.f, 0.f, 0.f, 0.f);
            if (bn < N) bv = *reinterpret_cast<const float4*>(&B[(size_t)bn * ldb + k0 + ac]);
            Bs[ac + 0][ar] = bv.x; Bs[ac + 1][ar] = bv.y; Bs[ac + 2][ar] = bv.z; Bs[ac + 3][ar] = bv.w;
        } else {
            int bk = tid >> 5;          // 0..7
            int bn = (tid & 31) * 4;    // 0..124
            int gn = colBase + bn;
            float4 bv = make_float4(0.f, 0.f, 0.f, 0.f);
            if (gn < N) bv = *reinterpret_cast<const float4*>(&B[(size_t)(k0 + bk) * ldb + gn]);
            *reinterpret_cast<float4*>(&Bs[bk][bn]) = bv;
        }
        __syncthreads();
#pragma unroll
        for (int k = 0; k < 8; k++) {
            float a[8], b[8];
            *reinterpret_cast<float4*>(&a[0]) = *reinterpret_cast<float4*>(&As[k][ty * 8]);
            *reinterpret_cast<float4*>(&a[4]) = *reinterpret_cast<float4*>(&As[k][ty * 8 + 4]);
            *reinterpret_cast<float4*>(&b[0]) = *reinterpret_cast<float4*>(&Bs[k][tx * 8]);
            *reinterpret_cast<float4*>(&b[4]) = *reinterpret_cast<float4*>(&Bs[k][tx * 8 + 4]);
#pragma unroll
            for (int i = 0; i < 8; i++)
#pragma unroll
                for (int j = 0; j < 8; j++) acc[i][j] = fmaf(a[i], b[j], acc[i][j]);
        }
        __syncthreads();
    }

#pragma unroll
    for (int i = 0; i < 8; i++) {
        int m = rowBase + ty * 8 + i;
        int orow = m;
        if (epi_mode) {
            int bb = m >> 13;
            int s  = m & (SEQLEN - 1);
            int tt = reverse ? (SEQLEN - 1 - s) : s;
            orow = (bb << 13) + tt;
        }
#pragma unroll
        for (int j = 0; j < 8; j++) {
            int col = colBase + tx * 8 + j;
            if (col < N) {
                float v = acc[i][j];
                if (epi_mode == 1)      C[(size_t)orow * ldc + col]  = v + (bias ? bias[col] : 0.f);
                else if (epi_mode == 2) C[(size_t)orow * ldc + col] += v;
                else                    C[(size_t)orow * ldc + col]  = v;
            }
        }
    }
}

// ---------------- causal depthwise conv + silu (direction-local s) ----------------
__global__ void k_conv(const float* __restrict__ conv_w, const float* __restrict__ conv_b, int dir)
{
    int idx = blockIdx.x * blockDim.x + threadIdx.x;
    if (idx >= BATCH * SEQLEN * CONVD) return;
    int c = idx % CONVD;
    int s = (idx / CONVD) % SEQLEN;
    int b = idx / (CONVD * SEQLEN);
    float acc = conv_b[c];
#pragma unroll
    for (int k = 0; k < 4; k++) {
        int sp = s - 3 + k;
        if (sp >= 0) {
            int t = dir ? (SEQLEN - 1 - sp) : sp;
            acc = fmaf(conv_w[c * 4 + k], g_zx[(size_t)(b * SEQLEN + t) * DPROJ + DIN + c], acc);
        }
    }
    g_xBC[(size_t)(b * SEQLEN + s) * CONVD + c] = acc / (1.f + expf(-acc));
}

// ---------------- dt = softplus(raw + bias), dta = A*dt ----------------
__global__ void k_dt(const float* __restrict__ dt_bias, const float* __restrict__ A_log, int dir)
{
    int idx = blockIdx.x * blockDim.x + threadIdx.x;
    if (idx >= BATCH * SEQLEN * NHEADS) return;
    int h = idx % NHEADS;
    int s = (idx / NHEADS) % SEQLEN;
    int b = idx / (NHEADS * SEQLEN);
    int t = dir ? (SEQLEN - 1 - s) : s;
    float x = g_zx[(size_t)(b * SEQLEN + t) * DPROJ + (DIN + CONVD) + h] + dt_bias[h];
    float dt = (x > 20.f) ? x : log1pf(expf(x));
    g_dt[idx]  = dt;
    g_dta[idx] = -expf(A_log[h]) * dt;
}

// ---------------- intra-chunk SSD: Y_diag + D-skip -> g_y, chunk states -> g_states ----------------
#define SMEM_CHUNK ((64*129 + 64*128 + 64*64 + 64*64 + 4*64) * 4)
__global__ void k_chunk(const float* __restrict__ D_skip)
{
    extern __shared__ float sm[];
    float* sB   = sm;                 // [64][129] padded
    float* sC   = sB + 64 * 129;      // [64][128]
    float* sX   = sC + 64 * 128;      // [64][64]  x*dt
    float* sG   = sX + 64 * 64;       // [64][64]
    float* sdt  = sG + 64 * 64;       // [64]
    float* sAc  = sdt + 64;           // [64]
    float* sDec = sAc + 64;           // [64]

    int h = blockIdx.x, c = blockIdx.y, b = blockIdx.z;
    int tid = threadIdx.x;
    int s0 = c * CH;

    if (tid < 64) {
        size_t r = (size_t)(b * SEQLEN + s0 + tid) * NHEADS + h;
        sdt[tid] = g_dt[r];
        sAc[tid] = g_dta[r];
    }
    __syncthreads();
    if (tid == 0) {
        float a = 0.f;
        for (int i = 0; i < 64; i++) { a += sAc[i]; sAc[i] = a; }
        g_Atot[(b * NHEADS + h) * NCH + c] = a;
    }
    __syncthreads();
    if (tid < 64) sDec[tid] = expf(sAc[63] - sAc[tid]);

    for (int i = tid; i < 64 * 128; i += 256) {
        int r = i >> 7, n = i & 127;
        const float* base = &g_xBC[(size_t)(b * SEQLEN + s0 + r) * CONVD];
        sB[r * 129 + n] = base[DIN + n];
        sC[r * 128 + n] = base[DIN + DSTATE + n];
    }
    for (int i = tid; i < 64 * 64; i += 256) {
        int r = i >> 6, p = i & 63;
        sX[i] = g_xBC[(size_t)(b * SEQLEN + s0 + r) * CONVD + h * HD + p] * sdt[r];
    }
    __syncthreads();

    // G[s][t] = (C[s]·B[t]) * exp(Acum[s]-Acum[t]) for t<=s
    for (int i = tid; i < 64 * 64; i += 256) {
        int s = i >> 6, t = i & 63;
        float v = 0.f;
        if (t <= s) {
            float d = 0.f;
#pragma unroll 8
            for (int n = 0; n < 128; n++) d = fmaf(sC[s * 128 + n], sB[t * 129 + n], d);
            v = d * expf(sAc[s] - sAc[t]);
        }
        sG[i] = v;
    }
    __syncthreads();

    // Y_diag + xh*D_skip
    float Dh = D_skip[h];
    for (int i = tid; i < 64 * 64; i += 256) {
        int s = i >> 6, p = i & 63;
        float acc = 0.f;
        for (int t = 0; t <= s; t++) acc = fmaf(sG[s * 64 + t], sX[t * 64 + p], acc);
        float xh = g_xBC[(size_t)(b * SEQLEN + s0 + s) * CONVD + h * HD + p];
        g_y[(size_t)(b * SEQLEN + s0 + s) * DIN + h * HD + p] = acc + xh * Dh;
    }

    // chunk states[p][n] = sum_t X[t][p]*B[t][n]*decay[t]
    for (int i = tid; i < HD * DSTATE; i += 256) {
        int p = i >> 7, n = i & 127;
        float acc = 0.f;
#pragma unroll 8
        for (int t = 0; t < 64; t++) acc = fmaf(sX[t * 64 + p] * sDec[t], sB[t * 129 + n], acc);
        g_states[((size_t)(b * NCH + c) * NHEADS + h) * (HD * DSTATE) + i] = acc;
    }
}

// ---------------- inter-chunk scan (elementwise over 8192 state elems; shared scalar decay) ----------------
__global__ void k_scan()
{
    __shared__ float sDec[NCH];
    int slice = blockIdx.x;     // 0..31
    int h = blockIdx.y, b = blockIdx.z;
    int tid = threadIdx.x;
    if (tid < NCH) sDec[tid] = expf(g_Atot[(b * NHEADS + h) * NCH + tid]);
    __syncthreads();
    int off = slice * 256 + tid;
    float s_in = 0.f;
    for (int c = 0; c < NCH; c++) {
        size_t idx = ((size_t)(b * NCH + c) * NHEADS + h) * (HD * DSTATE) + off;
        float cs = g_states[idx];
        g_states[idx] = s_in;                 // state entering chunk c
        s_in = fmaf(s_in, sDec[c], cs);
    }
}

// ---------------- Y_off + gating: y = (y + exp(Acum[s]) * C[s]·S) * silu(z) ----------------
#define SMEM_YOFF ((64*128 + 64*129 + 2*64) * 4)
__global__ void k_yoff(int dir)
{
    extern __shared__ float sm[];
    float* sC  = sm;                  // [64][128]
    float* sS  = sC + 64 * 128;       // [64(p)][129] padded
    float* sAc = sS + 64 * 129;       // [64]
    float* sE  = sAc + 64;            // [64]

    int h = blockIdx.x, c = blockIdx.y, b = blockIdx.z;
    int tid = threadIdx.x;
    int s0 = c * CH;

    if (tid < 64) sAc[tid] = g_dta[(size_t)(b * SEQLEN + s0 + tid) * NHEADS + h];
    __syncthreads();
    if (tid == 0) { float a = 0.f; for (int i = 0; i < 64; i++) { a += sAc[i]; sAc[i] = a; } }
    __syncthreads();
    if (tid < 64) sE[tid] = expf(sAc[tid]);

    for (int i = tid; i < 64 * 128; i += 256) {
        int r = i >> 7, n = i & 127;
        sC[r * 128 + n] = g_xBC[(size_t)(b * SEQLEN + s0 + r) * CONVD + DIN + DSTATE + n];
        sS[r * 129 + n] = g_states[((size_t)(b * NCH + c) * NHEADS + h) * (HD * DSTATE) + i];
    }
    __syncthreads();

    for (int i = tid; i < 64 * 64; i += 256) {
        int s = i >> 6, p = i & 63;
        float acc = 0.f;
#pragma unroll 8
        for (int n = 0; n < 128; n++) acc = fmaf(sC[s * 128 + n], sS[p * 129 + n], acc);
        size_t yi = (size_t)(b * SEQLEN + s0 + s) * DIN + h * HD + p;
        float y = g_y[yi] + acc * sE[s];
        int t = dir ? (SEQLEN - 1 - (s0 + s)) : (s0 + s);
        float z = g_zx[(size_t)(b * SEQLEN + t) * DPROJ + h * HD + p];
        y *= z / (1.f + expf(-z));
        g_y[yi] = y;
    }
}

// ---------------- RMS norm (per token over 1024) ----------------
__global__ void k_rms(const float* __restrict__ norm_w)
{
    __shared__ float red[256];
    int row = blockIdx.x;
    int tid = threadIdx.x;
    float* y = &g_y[(size_t)row * DIN];
    float v[4]; float ss = 0.f;
#pragma unroll
    for (int i = 0; i < 4; i++) { v[i] = y[tid + 256 * i]; ss = fmaf(v[i], v[i], ss); }
    red[tid] = ss;
    __syncthreads();
    for (int st = 128; st > 0; st >>= 1) { if (tid < st) red[tid] += red[tid + st]; __syncthreads(); }
    float scale = rsqrtf(red[0] * (1.f / 1024.f) + 1e-5f);
#pragma unroll
    for (int i = 0; i < 4; i++) y[tid + 256 * i] = v[i] * scale * norm_w[tid + 256 * i];
}

// ---------------- launch ----------------
extern "C" void kernel_launch(void* const* d_in, const int* in_sizes, int n_in,
                              void* d_out, int out_size)
{
    const float* x         = (const float*)d_in[0];
    const float* in_proj_w = (const float*)d_in[1];
    const float* conv_w    = (const float*)d_in[2];
    const float* conv_b    = (const float*)d_in[3];
    const float* dt_bias   = (const float*)d_in[4];
    const float* A_log     = (const float*)d_in[5];
    const float* D_skip    = (const float*)d_in[6];
    const float* norm_w    = (const float*)d_in[7];
    const float* ssm_out_w = (const float*)d_in[8];
    const float* fuse_w    = (const float*)d_in[9];
    const float* fuse_b    = (const float*)d_in[10];
    float* out = (float*)d_out;

    cudaFuncSetAttribute(k_chunk, cudaFuncAttributeMaxDynamicSharedMemorySize, SMEM_CHUNK);
    cudaFuncSetAttribute(k_yoff,  cudaFuncAttributeMaxDynamicSharedMemorySize, SMEM_YOFF);

    float *zx, *yb, *Wc;
    cudaGetSymbolAddress((void**)&zx, g_zx);
    cudaGetSymbolAddress((void**)&yb, g_y);
    cudaGetSymbolAddress((void**)&Wc, g_Wc);

    // 1) fused output weights: Wc[d] = fuse_w[:, d*512:(d+1)*512] @ ssm_out_w  (512x1024)
    {
        dim3 g(DIN / 128, DMODEL / 128);
        for (int d = 0; d < 2; d++)
            sgemm128<false><<<g, 256>>>(fuse_w + d * DMODEL, 2 * DMODEL,
                                        ssm_out_w, DIN,
                                        Wc + (size_t)d * DMODEL * DIN, DIN,
                                        DMODEL, DIN, DMODEL, nullptr, 0, 0);
    }

    // 2) in-projection (shared by both directions): zx = x @ in_proj_w^T
    {
        dim3 g((DPROJ + 127) / 128, (BATCH * SEQLEN) / 128);
        sgemm128<true><<<g, 256>>>(x, DMODEL, in_proj_w, DMODEL, zx, DPROJ,
                                   BATCH * SEQLEN, DPROJ, DMODEL, nullptr, 0, 0);
    }

    // 3) per-direction pipeline
    for (int dir = 0; dir < 2; dir++) {
        k_conv<<<(BATCH * SEQLEN * CONVD + 255) / 256, 256>>>(conv_w, conv_b, dir);
        k_dt<<<(BATCH * SEQLEN * NHEADS + 255) / 256, 256>>>(dt_bias, A_log, dir);

        dim3 gch(NHEADS, NCH, BATCH);
        k_chunk<<<gch, 256, SMEM_CHUNK>>>(D_skip);

        dim3 gsc(32, NHEADS, BATCH);
        k_scan<<<gsc, 256>>>();

        k_yoff<<<gch, 256, SMEM_YOFF>>>(dir);

        k_rms<<<BATCH * SEQLEN, 256>>>(norm_w);

        dim3 gf(DMODEL / 128, (BATCH * SEQLEN) / 128);
        sgemm128<true><<<gf, 256>>>(yb, DIN,
                                    Wc + (size_t)dir * DMODEL * DIN, DIN,
                                    out, DMODEL,
                                    BATCH * SEQLEN, DMODEL, DIN,
                                    dir == 0 ? fuse_b : nullptr,
                                    dir == 0 ? 1 : 2, dir);
    }
}

// round 2
// speedup vs baseline: 1.2702x; 1.2702x over previous
#include <cuda_runtime.h>
#include <math.h>

#define BATCH   2
#define SEQLEN  8192
#define DMODEL  512
#define DIN     1024
#define NHEADS  16
#define HD      64
#define DSTATE  128
#define CONVD   1280
#define DPROJ   2320
#define NCH     128
#define CH      64

// ---------------- scratch (static device memory; no allocations) ----------------
__device__ float g_zx[(size_t)BATCH*SEQLEN*DPROJ];
__device__ float g_xBC[(size_t)BATCH*SEQLEN*CONVD];
__device__ float g_dt[(size_t)BATCH*SEQLEN*NHEADS];
__device__ float g_dta[(size_t)BATCH*SEQLEN*NHEADS];
__device__ float g_Atot[BATCH*NHEADS*NCH];
__device__ float g_states[(size_t)BATCH*NCH*NHEADS*HD*DSTATE];
__device__ float g_y[(size_t)BATCH*SEQLEN*DIN];
__device__ float g_Wc[2*DMODEL*DIN];

// ---------------- double-buffered fp32 GEMM: C[M,N] = A[M,K] @ (BT ? B[N,K]^T : B[K,N]) ----------------
// 128x128 block, BK=8, 256 threads, 8x8 microtile, 2-stage smem pipeline.
// epi_mode: 0 plain store; 1 final write (+bias, row remap); 2 final accumulate (row remap).
template<bool BT>
__global__ __launch_bounds__(256, 2) void sgemm128(
    const float* __restrict__ A, int lda,
    const float* __restrict__ B, int ldb,
    float* __restrict__ C, int ldc,
    int M, int N, int K,
    const float* __restrict__ bias,
    int epi_mode, int reverse,
    int aoffZ, int coffZ)
{
    __shared__ float As[2][8][128];
    __shared__ float Bs[2][8][128];
    A += (size_t)blockIdx.z * aoffZ;
    C += (size_t)blockIdx.z * coffZ;

    int tid = threadIdx.x;
    int tx = tid & 15, ty = tid >> 4;
    int rowBase = blockIdx.y * 128;
    int colBase = blockIdx.x * 128;
    float acc[8][8];
#pragma unroll
    for (int i = 0; i < 8; i++)
#pragma unroll
        for (int j = 0; j < 8; j++) acc[i][j] = 0.f;

    int ar = tid >> 1;          // 0..127
    int ac = (tid & 1) * 4;     // 0 or 4
    int bk = tid >> 5;          // 0..7   (BT=false layout)
    int bn = (tid & 31) * 4;    // 0..124

    // load tile 0
    float4 av = *reinterpret_cast<const float4*>(&A[(size_t)(rowBase + ar) * lda + ac]);
    float4 bv = make_float4(0.f, 0.f, 0.f, 0.f);
    if (BT) {
        int n = colBase + ar;
        if (n < N) bv = *reinterpret_cast<const float4*>(&B[(size_t)n * ldb + ac]);
    } else {
        int gn = colBase + bn;
        if (gn < N) bv = *reinterpret_cast<const float4*>(&B[(size_t)bk * ldb + gn]);
    }
    As[0][ac + 0][ar] = av.x; As[0][ac + 1][ar] = av.y; As[0][ac + 2][ar] = av.z; As[0][ac + 3][ar] = av.w;
    if (BT) { Bs[0][ac + 0][ar] = bv.x; Bs[0][ac + 1][ar] = bv.y; Bs[0][ac + 2][ar] = bv.z; Bs[0][ac + 3][ar] = bv.w; }
    else    { *reinterpret_cast<float4*>(&Bs[0][bk][bn]) = bv; }
    __syncthreads();

    int nt = K >> 3;
    for (int t = 0; t < nt; t++) {
        int buf = t & 1;
        if (t + 1 < nt) {
            int k0 = (t + 1) * 8;
            av = *reinterpret_cast<const float4*>(&A[(size_t)(rowBase + ar) * lda + k0 + ac]);
            bv = make_float4(0.f, 0.f, 0.f, 0.f);
            if (BT) {
                int n = colBase + ar;
                if (n < N) bv = *reinterpret_cast<const float4*>(&B[(size_t)n * ldb + k0 + ac]);
            } else {
                int gn = colBase + bn;
                if (gn < N) bv = *reinterpret_cast<const float4*>(&B[(size_t)(k0 + bk) * ldb + gn]);
            }
        }
#pragma unroll
        for (int k = 0; k < 8; k++) {
            float a[8], b[8];
            *reinterpret_cast<float4*>(&a[0]) = *reinterpret_cast<float4*>(&As[buf][k][ty * 8]);
            *reinterpret_cast<float4*>(&a[4]) = *reinterpret_cast<float4*>(&As[buf][k][ty * 8 + 4]);
            *reinterpret_cast<float4*>(&b[0]) = *reinterpret_cast<float4*>(&Bs[buf][k][tx * 8]);
            *reinterpret_cast<float4*>(&b[4]) = *reinterpret_cast<float4*>(&Bs[buf][k][tx * 8 + 4]);
#pragma unroll
            for (int i = 0; i < 8; i++)
#pragma unroll
                for (int j = 0; j < 8; j++) acc[i][j] = fmaf(a[i], b[j], acc[i][j]);
        }
        if (t + 1 < nt) {
            int nb = buf ^ 1;
            As[nb][ac + 0][ar] = av.x; As[nb][ac + 1][ar] = av.y; As[nb][ac + 2][ar] = av.z; As[nb][ac + 3][ar] = av.w;
            if (BT) { Bs[nb][ac + 0][ar] = bv.x; Bs[nb][ac + 1][ar] = bv.y; Bs[nb][ac + 2][ar] = bv.z; Bs[nb][ac + 3][ar] = bv.w; }
            else    { *reinterpret_cast<float4*>(&Bs[nb][bk][bn]) = bv; }
            __syncthreads();
        }
    }

#pragma unroll
    for (int i = 0; i < 8; i++) {
        int m = rowBase + ty * 8 + i;
        int orow = m;
        if (epi_mode) {
            int bb = m >> 13;
            int s  = m & (SEQLEN - 1);
            int tt = reverse ? (SEQLEN - 1 - s) : s;
            orow = (bb << 13) + tt;
        }
#pragma unroll
        for (int j = 0; j < 8; j++) {
            int col = colBase + tx * 8 + j;
            if (col < N) {
                float v = acc[i][j];
                if (epi_mode == 1)      C[(size_t)orow * ldc + col]  = v + (bias ? bias[col] : 0.f);
                else if (epi_mode == 2) C[(size_t)orow * ldc + col] += v;
                else                    C[(size_t)orow * ldc + col]  = v;
            }
        }
    }
}

// ---------------- causal depthwise conv + silu, rolling window (16 s per thread) ----------------
__global__ void k_conv(const float* __restrict__ conv_w, const float* __restrict__ conv_b, int dir)
{
    int c  = blockIdx.x * 256 + threadIdx.x;     // gridDim.x = CONVD/256 = 5
    int b  = blockIdx.z;
    int s0 = blockIdx.y * 16;
    float w0 = conv_w[c * 4 + 0], w1 = conv_w[c * 4 + 1], w2 = conv_w[c * 4 + 2], w3 = conv_w[c * 4 + 3];
    float cb = conv_b[c];
    float x0 = 0.f, x1 = 0.f, x2 = 0.f;
#pragma unroll
    for (int j = 0; j < 3; j++) {
        int sp = s0 - 3 + j;
        float v = 0.f;
        if (sp >= 0) {
            int t = dir ? (SEQLEN - 1 - sp) : sp;
            v = g_zx[(size_t)(b * SEQLEN + t) * DPROJ + DIN + c];
        }
        if (j == 0) x0 = v; else if (j == 1) x1 = v; else x2 = v;
    }
#pragma unroll
    for (int i = 0; i < 16; i++) {
        int sp = s0 + i;
        int t  = dir ? (SEQLEN - 1 - sp) : sp;
        float x3 = g_zx[(size_t)(b * SEQLEN + t) * DPROJ + DIN + c];
        float a = fmaf(w0, x0, fmaf(w1, x1, fmaf(w2, x2, fmaf(w3, x3, cb))));
        g_xBC[(size_t)(b * SEQLEN + sp) * CONVD + c] = a / (1.f + __expf(-a));
        x0 = x1; x1 = x2; x2 = x3;
    }
}

// ---------------- dt = softplus(raw + bias), dta = A*dt ----------------
__global__ void k_dt(const float* __restrict__ dt_bias, const float* __restrict__ A_log, int dir)
{
    int idx = blockIdx.x * blockDim.x + threadIdx.x;
    if (idx >= BATCH * SEQLEN * NHEADS) return;
    int h = idx % NHEADS;
    int s = (idx / NHEADS) % SEQLEN;
    int b = idx / (NHEADS * SEQLEN);
    int t = dir ? (SEQLEN - 1 - s) : s;
    float x = g_zx[(size_t)(b * SEQLEN + t) * DPROJ + (DIN + CONVD) + h] + dt_bias[h];
    float dt = (x > 20.f) ? x : log1pf(expf(x));
    g_dt[idx]  = dt;
    g_dta[idx] = -expf(A_log[h]) * dt;
}

// ---------------- intra-chunk SSD, register-tiled ----------------
// smem floats: sCt 128*68 + sBt 128*68 + sBn 64*132 + sX 64*68 + sXh 64*68 + sGt 64*68 + 192
#define SMEM_CHUNK ((128*68*2 + 64*132 + 64*68*3 + 192) * 4)
__global__ __launch_bounds__(256) void k_chunk(const float* __restrict__ D_skip)
{
    extern __shared__ float sm[];
    float* sCt = sm;                 // [128 n][68]  C^T
    float* sBt = sCt + 128 * 68;     // [128 n][68]  B^T
    float* sBn = sBt + 128 * 68;     // [64 t][132]  B natural
    float* sX  = sBn + 64 * 132;     // [64 t][68]   x*dt
    float* sXh = sX  + 64 * 68;      // [64 t][68]   x
    float* sGt = sXh + 64 * 68;      // [64 t][68]   G^T
    float* sAc = sGt + 64 * 68;      // [64]
    float* sDec= sAc + 64;           // [64]
    float* sdt = sDec + 64;          // [64]

    int h = blockIdx.x, c = blockIdx.y, b = blockIdx.z;
    int tid = threadIdx.x;
    int s0g = c * CH;
    size_t rowbase = (size_t)(b * SEQLEN + s0g);

    if (tid < 64) {
        size_t r = (rowbase + tid) * NHEADS + h;
        sdt[tid] = g_dt[r];
        sAc[tid] = g_dta[r];
    }
    __syncthreads();
    if (tid == 0) {
        float a = 0.f;
        for (int i = 0; i < 64; i++) { a += sAc[i]; sAc[i] = a; }
        g_Atot[(b * NHEADS + h) * NCH + c] = a;
    }
    __syncthreads();
    if (tid < 64) sDec[tid] = __expf(sAc[63] - sAc[tid]);

    for (int i = tid; i < 64 * 128; i += 256) {
        int r = i >> 7, n = i & 127;
        const float* base = &g_xBC[(rowbase + r) * CONVD];
        float vB = base[DIN + n];
        sBt[n * 68 + r] = vB;
        sBn[r * 132 + n] = vB;
        sCt[n * 68 + r] = base[DIN + DSTATE + n];
    }
    for (int i = tid; i < 64 * 64; i += 256) {
        int r = i >> 6, p = i & 63;
        float v = g_xBC[(rowbase + r) * CONVD + h * HD + p];
        sXh[r * 68 + p] = v;
        sX[r * 68 + p]  = v * sdt[r];
    }
    __syncthreads();

    int tx = tid & 15, ty = tid >> 4;

    // ---- G[s][t] = (C[s]·B[t]) * exp(Ac[s]-Ac[t]), t<=s; stored transposed sGt[t][s] ----
    {
        int s0 = ty * 4, t0 = tx * 4;
        float g[4][4];
#pragma unroll
        for (int i = 0; i < 4; i++)
#pragma unroll
            for (int j = 0; j < 4; j++) g[i][j] = 0.f;
        if (tx <= ty) {
#pragma unroll 4
            for (int n = 0; n < 128; n++) {
                float4 a4 = *reinterpret_cast<float4*>(&sCt[n * 68 + s0]);
                float4 b4 = *reinterpret_cast<float4*>(&sBt[n * 68 + t0]);
                float a[4] = {a4.x, a4.y, a4.z, a4.w};
                float bb[4] = {b4.x, b4.y, b4.z, b4.w};
#pragma unroll
                for (int i = 0; i < 4; i++)
#pragma unroll
                    for (int j = 0; j < 4; j++) g[i][j] = fmaf(a[i], bb[j], g[i][j]);
            }
#pragma unroll
            for (int i = 0; i < 4; i++)
#pragma unroll
                for (int j = 0; j < 4; j++) {
                    int s = s0 + i, t = t0 + j;
                    g[i][j] = (t <= s) ? g[i][j] * __expf(sAc[s] - sAc[t]) : 0.f;
                }
        }
#pragma unroll
        for (int i = 0; i < 4; i++)
#pragma unroll
            for (int j = 0; j < 4; j++) sGt[(t0 + j) * 68 + s0 + i] = g[i][j];
    }
    __syncthreads();

    // ---- Y_diag[s][p] = sum_t G[s][t]*X[t][p]  (+ xh*D_skip) ----
    {
        int s0 = ty * 4, p0 = tx * 4;
        float y[4][4];
#pragma unroll
        for (int i = 0; i < 4; i++)
#pragma unroll
            for (int j = 0; j < 4; j++) y[i][j] = 0.f;
        int tmax = s0 + 4;
        for (int t = 0; t < tmax; t++) {
            float4 a4 = *reinterpret_cast<float4*>(&sGt[t * 68 + s0]);
            float4 b4 = *reinterpret_cast<float4*>(&sX[t * 68 + p0]);
            float a[4] = {a4.x, a4.y, a4.z, a4.w};
            float bb[4] = {b4.x, b4.y, b4.z, b4.w};
#pragma unroll
            for (int i = 0; i < 4; i++)
#pragma unroll
                for (int j = 0; j < 4; j++) y[i][j] = fmaf(a[i], bb[j], y[i][j]);
        }
        float Dh = D_skip[h];
#pragma unroll
        for (int i = 0; i < 4; i++) {
            int s = s0 + i;
            float4 o;
            o.x = y[i][0] + sXh[s * 68 + p0 + 0] * Dh;
            o.y = y[i][1] + sXh[s * 68 + p0 + 1] * Dh;
            o.z = y[i][2] + sXh[s * 68 + p0 + 2] * Dh;
            o.w = y[i][3] + sXh[s * 68 + p0 + 3] * Dh;
            *reinterpret_cast<float4*>(&g_y[(rowbase + s) * DIN + h * HD + p0]) = o;
        }
    }

    // ---- chunk states S[p][n] = sum_t X[t][p]*dec[t]*B[t][n] ----
    {
        int n0 = tx * 8, p0 = ty * 4;
        float acc[4][8];
#pragma unroll
        for (int i = 0; i < 4; i++)
#pragma unroll
            for (int j = 0; j < 8; j++) acc[i][j] = 0.f;
#pragma unroll 2
        for (int t = 0; t < 64; t++) {
            float dec = sDec[t];
            float4 xv = *reinterpret_cast<float4*>(&sX[t * 68 + p0]);
            float xa[4] = {xv.x * dec, xv.y * dec, xv.z * dec, xv.w * dec};
            float4 b0 = *reinterpret_cast<float4*>(&sBn[t * 132 + n0]);
            float4 b1 = *reinterpret_cast<float4*>(&sBn[t * 132 + n0 + 4]);
            float bb[8] = {b0.x, b0.y, b0.z, b0.w, b1.x, b1.y, b1.z, b1.w};
#pragma unroll
            for (int i = 0; i < 4; i++)
#pragma unroll
                for (int j = 0; j < 8; j++) acc[i][j] = fmaf(xa[i], bb[j], acc[i][j]);
        }
        size_t sb = ((size_t)(b * NCH + c) * NHEADS + h) * (HD * DSTATE);
#pragma unroll
        for (int i = 0; i < 4; i++) {
            *reinterpret_cast<float4*>(&g_states[sb + (p0 + i) * DSTATE + n0])     = make_float4(acc[i][0], acc[i][1], acc[i][2], acc[i][3]);
            *reinterpret_cast<float4*>(&g_states[sb + (p0 + i) * DSTATE + n0 + 4]) = make_float4(acc[i][4], acc[i][5], acc[i][6], acc[i][7]);
        }
    }
}

// ---------------- inter-chunk scan ----------------
__global__ void k_scan()
{
    __shared__ float sDec[NCH];
    int slice = blockIdx.x;     // 0..31
    int h = blockIdx.y, b = blockIdx.z;
    int tid = threadIdx.x;
    if (tid < NCH) sDec[tid] = expf(g_Atot[(b * NHEADS + h) * NCH + tid]);
    __syncthreads();
    int off = slice * 256 + tid;
    float s_in = 0.f;
    for (int c = 0; c < NCH; c++) {
        size_t idx = ((size_t)(b * NCH + c) * NHEADS + h) * (HD * DSTATE) + off;
        float cs = g_states[idx];
        g_states[idx] = s_in;
        s_in = fmaf(s_in, sDec[c], cs);
    }
}

// ---------------- Y_off + gating, register-tiled ----------------
#define SMEM_YOFF ((128*68*2 + 128) * 4)
__global__ __launch_bounds__(256) void k_yoff(int dir)
{
    extern __shared__ float sm[];
    float* sCt = sm;                 // [128 n][68]
    float* sSt = sCt + 128 * 68;     // [128 n][68]   S^T (n-major)
    float* sAc = sSt + 128 * 68;     // [64]
    float* sE  = sAc + 64;           // [64]

    int h = blockIdx.x, c = blockIdx.y, b = blockIdx.z;
    int tid = threadIdx.x;
    int s0g = c * CH;
    size_t rowbase = (size_t)(b * SEQLEN + s0g);

    if (tid < 64) sAc[tid] = g_dta[(rowbase + tid) * NHEADS + h];
    __syncthreads();
    if (tid == 0) { float a = 0.f; for (int i = 0; i < 64; i++) { a += sAc[i]; sAc[i] = a; } }
    __syncthreads();
    if (tid < 64) sE[tid] = __expf(sAc[tid]);

    size_t sb = ((size_t)(b * NCH + c) * NHEADS + h) * (HD * DSTATE);
    for (int i = tid; i < 64 * 128; i += 256) {
        int r = i >> 7, n = i & 127;
        sCt[n * 68 + r] = g_xBC[(rowbase + r) * CONVD + DIN + DSTATE + n];
        sSt[n * 68 + r] = g_states[sb + i];     // r == p
    }
    __syncthreads();

    int tx = tid & 15, ty = tid >> 4;
    int s0 = ty * 4, p0 = tx * 4;
    float acc[4][4];
#pragma unroll
    for (int i = 0; i < 4; i++)
#pragma unroll
        for (int j = 0; j < 4; j++) acc[i][j] = 0.f;
#pragma unroll 4
    for (int n = 0; n < 128; n++) {
        float4 a4 = *reinterpret_cast<float4*>(&sCt[n * 68 + s0]);
        float4 b4 = *reinterpret_cast<float4*>(&sSt[n * 68 + p0]);
        float a[4] = {a4.x, a4.y, a4.z, a4.w};
        float bb[4] = {b4.x, b4.y, b4.z, b4.w};
#pragma unroll
        for (int i = 0; i < 4; i++)
#pragma unroll
            for (int j = 0; j < 4; j++) acc[i][j] = fmaf(a[i], bb[j], acc[i][j]);
    }
#pragma unroll
    for (int i = 0; i < 4; i++) {
        int s = s0 + i;
        size_t yi = (rowbase + s) * DIN + h * HD + p0;
        float4 yv = *reinterpret_cast<float4*>(&g_y[yi]);
        int t = dir ? (SEQLEN - 1 - (s0g + s)) : (s0g + s);
        const float* zp = &g_zx[(size_t)(b * SEQLEN + t) * DPROJ + h * HD + p0];
        float4 zv = *reinterpret_cast<const float4*>(zp);
        float e = sE[s];
        float4 o;
        float yv0 = yv.x + acc[i][0] * e;
        float yv1 = yv.y + acc[i][1] * e;
        float yv2 = yv.z + acc[i][2] * e;
        float yv3 = yv.w + acc[i][3] * e;
        o.x = yv0 * (zv.x / (1.f + __expf(-zv.x)));
        o.y = yv1 * (zv.y / (1.f + __expf(-zv.y)));
        o.z = yv2 * (zv.z / (1.f + __expf(-zv.z)));
        o.w = yv3 * (zv.w / (1.f + __expf(-zv.w)));
        *reinterpret_cast<float4*>(&g_y[yi]) = o;
    }
}

// ---------------- RMS norm (per token over 1024), float4 ----------------
__global__ void k_rms(const float* __restrict__ norm_w)
{
    __shared__ float red[256];
    int row = blockIdx.x;
    int tid = threadIdx.x;
    float4* y = reinterpret_cast<float4*>(&g_y[(size_t)row * DIN]);
    float4 v = y[tid];
    float ss = v.x * v.x + v.y * v.y + v.z * v.z + v.w * v.w;
    red[tid] = ss;
    __syncthreads();
    for (int st = 128; st > 0; st >>= 1) { if (tid < st) red[tid] += red[tid + st]; __syncthreads(); }
    float scale = rsqrtf(red[0] * (1.f / 1024.f) + 1e-5f);
    float4 w = reinterpret_cast<const float4*>(norm_w)[tid];
    v.x *= scale * w.x; v.y *= scale * w.y; v.z *= scale * w.z; v.w *= scale * w.w;
    y[tid] = v;
}

// ---------------- launch ----------------
extern "C" void kernel_launch(void* const* d_in, const int* in_sizes, int n_in,
                              void* d_out, int out_size)
{
    const float* x         = (const float*)d_in[0];
    const float* in_proj_w = (const float*)d_in[1];
    const float* conv_w    = (const float*)d_in[2];
    const float* conv_b    = (const float*)d_in[3];
    const float* dt_bias   = (const float*)d_in[4];
    const float* A_log     = (const float*)d_in[5];
    const float* D_skip    = (const float*)d_in[6];
    const float* norm_w    = (const float*)d_in[7];
    const float* ssm_out_w = (const float*)d_in[8];
    const float* fuse_w    = (const float*)d_in[9];
    const float* fuse_b    = (const float*)d_in[10];
    float* out = (float*)d_out;

    cudaFuncSetAttribute(k_chunk, cudaFuncAttributeMaxDynamicSharedMemorySize, SMEM_CHUNK);
    cudaFuncSetAttribute(k_yoff,  cudaFuncAttributeMaxDynamicSharedMemorySize, SMEM_YOFF);

    float *zx, *yb, *Wc;
    cudaGetSymbolAddress((void**)&zx, g_zx);
    cudaGetSymbolAddress((void**)&yb, g_y);
    cudaGetSymbolAddress((void**)&Wc, g_Wc);

    // 1) fused output weights: Wc[d] = fuse_w[:, d*512:(d+1)*512] @ ssm_out_w  (512x1024), both d in one launch
    {
        dim3 g(DIN / 128, DMODEL / 128, 2);
        sgemm128<false><<<g, 256>>>(fuse_w, 2 * DMODEL,
                                    ssm_out_w, DIN,
                                    Wc, DIN,
                                    DMODEL, DIN, DMODEL, nullptr, 0, 0,
                                    DMODEL, DMODEL * DIN);
    }

    // 2) in-projection (shared by both directions): zx = x @ in_proj_w^T
    {
        dim3 g((DPROJ + 127) / 128, (BATCH * SEQLEN) / 128, 1);
        sgemm128<true><<<g, 256>>>(x, DMODEL, in_proj_w, DMODEL, zx, DPROJ,
                                   BATCH * SEQLEN, DPROJ, DMODEL, nullptr, 0, 0, 0, 0);
    }

    // 3) per-direction pipeline
    for (int dir = 0; dir < 2; dir++) {
        dim3 gc(CONVD / 256, SEQLEN / 16, BATCH);
        k_conv<<<gc, 256>>>(conv_w, conv_b, dir);
        k_dt<<<(BATCH * SEQLEN * NHEADS + 255) / 256, 256>>>(dt_bias, A_log, dir);

        dim3 gch(NHEADS, NCH, BATCH);
        k_chunk<<<gch, 256, SMEM_CHUNK>>>(D_skip);

        dim3 gsc(32, NHEADS, BATCH);
        k_scan<<<gsc, 256>>>();

        k_yoff<<<gch, 256, SMEM_YOFF>>>(dir);

        k_rms<<<BATCH * SEQLEN, 256>>>(norm_w);

        dim3 gf(DMODEL / 128, (BATCH * SEQLEN) / 128, 1);
        sgemm128<true><<<gf, 256>>>(yb, DIN,
                                    Wc + (size_t)dir * DMODEL * DIN, DIN,
                                    out, DMODEL,
                                    BATCH * SEQLEN, DMODEL, DIN,
                                    dir == 0 ? fuse_b : nullptr,
                                    dir == 0 ? 1 : 2, dir, 0, 0);
    }
}